// round 1
// baseline (speedup 1.0000x reference)
#include <cuda_runtime.h>
#include <cuda_bf16.h>

#define NND 100000
#define NE  1600000
#define NG  128
#define DD  128
#define OUTD 64
#define NL  4
#define BN_EPS 1e-5f

// ---------------- scratch (device globals; no allocation) ----------------
__device__ float g_P[NND * DD];     // pooled = agg + (1+eps)h
__device__ float g_Z[NND * DD];     // gemm output (pre-BN)
__device__ float g_Y[NND * DD];     // MLP hidden activation
__device__ float g_H[NND * DD];     // layer output h
__device__ float g_stats[2 * DD];   // per-channel sum / sumsq
__device__ float g_pg[(NL + 1) * NG * DD];  // graph-pooled hiddens

// ---------------- helpers ----------------
__device__ __forceinline__ void red_add_v4(float* addr, float4 v) {
    asm volatile("red.global.add.v4.f32 [%0], {%1, %2, %3, %4};"
                 :: "l"(addr), "f"(v.x), "f"(v.y), "f"(v.z), "f"(v.w)
                 : "memory");
}

// ---------------- kernels ----------------

// P = (1 + eps[l]) * in     (one float4 per thread)
__global__ void k_init_pooled(const float* __restrict__ in,
                              const float* __restrict__ eps, int l) {
    int idx = blockIdx.x * blockDim.x + threadIdx.x;   // float4 index
    if (idx >= NND * (DD / 4)) return;
    float e = 1.0f + __ldg(&eps[l]);
    float4 v = ((const float4*)in)[idx];
    v.x *= e; v.y *= e; v.z *= e; v.w *= e;
    ((float4*)g_P)[idx] = v;
}

// P[dst] += in[src]  via vector red; one warp per edge
__global__ void k_edge(const float* __restrict__ in,
                       const int* __restrict__ src,
                       const int* __restrict__ dst) {
    int gw = (blockIdx.x * blockDim.x + threadIdx.x) >> 5;
    int lane = threadIdx.x & 31;
    if (gw >= NE) return;
    int s = __ldg(&src[gw]);
    int d = __ldg(&dst[gw]);
    float4 v = ((const float4*)in)[s * (DD / 4) + lane];
    red_add_v4(&g_P[d * DD + lane * 4], v);
}

// Z[M,128] = A[M,128] @ W[128,128] + bias
// tile: 64 rows/block, 256 threads, 8 rows x 4 cols per thread
__global__ void __launch_bounds__(256, 2)
k_gemm(float* __restrict__ out, const float* __restrict__ A,
       const float* __restrict__ W, const float* __restrict__ bias, int M) {
    extern __shared__ float smem[];
    float* Ws = smem;            // [128][128]
    float* At = smem + DD * DD;  // [128][64] transposed A tile

    int t = threadIdx.x;
    int c = t & 31;    // col quad -> cols 4c..4c+3
    int rg = t >> 5;   // row group -> rows 8rg..8rg+7
    int m0 = blockIdx.x * 64;

    // load W (128x128 floats = 4096 float4)
    const float4* W4 = (const float4*)W;
#pragma unroll
    for (int i = 0; i < 16; i++)
        ((float4*)Ws)[t + i * 256] = W4[t + i * 256];

    // load+transpose A tile (64x128 = 2048 float4)
    const float4* A4 = (const float4*)A;
#pragma unroll
    for (int i = 0; i < 8; i++) {
        int fi = t + i * 256;
        int row = fi >> 5;       // 0..63
        int kq = fi & 31;        // k quad
        float4 v = make_float4(0.f, 0.f, 0.f, 0.f);
        int grow = m0 + row;
        if (grow < M) v = A4[grow * 32 + kq];
        int kb = kq * 4;
        At[(kb + 0) * 64 + row] = v.x;
        At[(kb + 1) * 64 + row] = v.y;
        At[(kb + 2) * 64 + row] = v.z;
        At[(kb + 3) * 64 + row] = v.w;
    }
    __syncthreads();

    float acc[8][4];
#pragma unroll
    for (int i = 0; i < 8; i++)
#pragma unroll
        for (int j = 0; j < 4; j++) acc[i][j] = 0.f;

#pragma unroll 4
    for (int k = 0; k < DD; k++) {
        float4 w = *(const float4*)&Ws[k * DD + c * 4];
        float4 a0 = *(const float4*)&At[k * 64 + rg * 8];
        float4 a1 = *(const float4*)&At[k * 64 + rg * 8 + 4];
        float av[8] = {a0.x, a0.y, a0.z, a0.w, a1.x, a1.y, a1.z, a1.w};
#pragma unroll
        for (int i = 0; i < 8; i++) {
            acc[i][0] += av[i] * w.x;
            acc[i][1] += av[i] * w.y;
            acc[i][2] += av[i] * w.z;
            acc[i][3] += av[i] * w.w;
        }
    }

    float4 b = *(const float4*)&bias[c * 4];
#pragma unroll
    for (int i = 0; i < 8; i++) {
        int row = m0 + rg * 8 + i;
        if (row < M) {
            float4 o = make_float4(acc[i][0] + b.x, acc[i][1] + b.y,
                                   acc[i][2] + b.z, acc[i][3] + b.w);
            ((float4*)out)[row * 32 + c] = o;
        }
    }
}

// per-channel sum + sumsq (into pre-zeroed g_stats)
__global__ void k_stats(const float* __restrict__ Z) {
    __shared__ float sbuf[8][DD];
    __shared__ float qbuf[8][DD];
    int t = threadIdx.x;
    int lane = t & 31;
    int w = t >> 5;
    int gwarp = blockIdx.x * 8 + w;
    int stride = gridDim.x * 8;

    float4 s = make_float4(0.f, 0.f, 0.f, 0.f);
    float4 q = make_float4(0.f, 0.f, 0.f, 0.f);
    for (int row = gwarp; row < NND; row += stride) {
        float4 v = ((const float4*)Z)[row * 32 + lane];
        s.x += v.x; s.y += v.y; s.z += v.z; s.w += v.w;
        q.x += v.x * v.x; q.y += v.y * v.y; q.z += v.z * v.z; q.w += v.w * v.w;
    }
    int ch = lane * 4;
    sbuf[w][ch] = s.x; sbuf[w][ch + 1] = s.y; sbuf[w][ch + 2] = s.z; sbuf[w][ch + 3] = s.w;
    qbuf[w][ch] = q.x; qbuf[w][ch + 1] = q.y; qbuf[w][ch + 2] = q.z; qbuf[w][ch + 3] = q.w;
    __syncthreads();
    if (t < DD) {
        float ss = 0.f, qq = 0.f;
#pragma unroll
        for (int i = 0; i < 8; i++) { ss += sbuf[i][t]; qq += qbuf[i][t]; }
        atomicAdd(&g_stats[t], ss);
        atomicAdd(&g_stats[DD + t], qq);
    }
}

// out = relu(g*(Z-mu)*rsqrt(var+eps)+be)
__global__ void k_bnrelu(float* __restrict__ out, const float* __restrict__ Z,
                         const float* __restrict__ gam, const float* __restrict__ bet) {
    __shared__ float sc[DD], sh[DD];
    int t = threadIdx.x;
    if (t < DD) {
        const float inv_n = 1.0f / (float)NND;
        float mu = g_stats[t] * inv_n;
        float var = g_stats[DD + t] * inv_n - mu * mu;
        float s = __ldg(&gam[t]) * rsqrtf(var + BN_EPS);
        sc[t] = s;
        sh[t] = __ldg(&bet[t]) - mu * s;
    }
    __syncthreads();
    int idx = blockIdx.x * blockDim.x + t;   // float4 index
    if (idx >= NND * 32) return;
    int ch = (idx & 31) * 4;
    float4 v = ((const float4*)Z)[idx];
    float4 o;
    o.x = fmaxf(v.x * sc[ch] + sh[ch], 0.f);
    o.y = fmaxf(v.y * sc[ch + 1] + sh[ch + 1], 0.f);
    o.z = fmaxf(v.z * sc[ch + 2] + sh[ch + 2], 0.f);
    o.w = fmaxf(v.w * sc[ch + 3] + sh[ch + 3], 0.f);
    ((float4*)out)[idx] = o;
}

// graph pooling: pg[gid] += h[node]  (warp per node, vector red)
__global__ void k_gpool(float* __restrict__ pg, const float* __restrict__ h,
                        const int* __restrict__ gids) {
    int gw = (blockIdx.x * blockDim.x + threadIdx.x) >> 5;
    int lane = threadIdx.x & 31;
    if (gw >= NND) return;
    int gid = __ldg(&gids[gw]);
    float4 v = ((const float4*)h)[gw * 32 + lane];
    red_add_v4(&pg[gid * DD + lane * 4], v);
}

// score[g][o] = sum_l pg[l][g] @ predW[l][:,o] + sum_l predb[l][o]
__global__ void k_readout(float* __restrict__ out,
                          const float* __restrict__ predW,
                          const float* __restrict__ predb) {
    int g = blockIdx.x;
    int o = threadIdx.x;
    float acc = 0.f;
#pragma unroll
    for (int l = 0; l < NL + 1; l++) {
        const float* pgrow = &g_pg[l * NG * DD + g * DD];
        const float* Wl = &predW[l * DD * OUTD];
        float a = 0.f;
        for (int k = 0; k < DD; k++)
            a += pgrow[k] * __ldg(&Wl[k * OUTD + o]);
        acc += a + __ldg(&predb[l * OUTD + o]);
    }
    out[g * OUTD + o] = acc;
}

// ---------------- launch ----------------
extern "C" void kernel_launch(void* const* d_in, const int* in_sizes, int n_in,
                              void* d_out, int out_size) {
    const float* x     = (const float*)d_in[0];
    const int* esrc    = (const int*)d_in[1];
    const int* edst    = (const int*)d_in[2];
    const int* gids    = (const int*)d_in[3];
    const float* eps   = (const float*)d_in[4];
    const float* W1    = (const float*)d_in[5];
    const float* b1    = (const float*)d_in[6];
    const float* g1    = (const float*)d_in[7];
    const float* be1   = (const float*)d_in[8];
    const float* W2    = (const float*)d_in[9];
    const float* b2    = (const float*)d_in[10];
    const float* g2    = (const float*)d_in[11];
    const float* be2   = (const float*)d_in[12];
    const float* predW = (const float*)d_in[13];
    const float* predb = (const float*)d_in[14];
    float* out = (float*)d_out;

    float *P, *Z, *Y, *H, *stats, *pg;
    cudaGetSymbolAddress((void**)&P, g_P);
    cudaGetSymbolAddress((void**)&Z, g_Z);
    cudaGetSymbolAddress((void**)&Y, g_Y);
    cudaGetSymbolAddress((void**)&H, g_H);
    cudaGetSymbolAddress((void**)&stats, g_stats);
    cudaGetSymbolAddress((void**)&pg, g_pg);

    static bool attr_set = false;
    if (!attr_set) {
        cudaFuncSetAttribute(k_gemm, cudaFuncAttributeMaxDynamicSharedMemorySize,
                             (DD * DD + DD * 64) * (int)sizeof(float));
        attr_set = true;
    }
    const int smem_gemm = (DD * DD + DD * 64) * (int)sizeof(float);

    const int nF4 = NND * (DD / 4);                // 3.2M float4
    const int gridElem = (nF4 + 255) / 256;        // 12500
    const int gridEdge = (NE + 7) / 8;             // warp/edge, 8 warps/block
    const int gridNode = (NND + 7) / 8;            // warp/node
    const int gridGemm = (NND + 63) / 64;

    // zero graph pools, pool layer-0 (= x)
    cudaMemsetAsync(pg, 0, sizeof(float) * (NL + 1) * NG * DD);
    k_gpool<<<gridNode, 256>>>(pg, x, gids);

    const float* hin = x;
    for (int l = 0; l < NL; l++) {
        k_init_pooled<<<gridElem, 256>>>(hin, eps, l);
        k_edge<<<gridEdge, 256>>>(hin, esrc, edst);

        k_gemm<<<gridGemm, 256, smem_gemm>>>(Z, P, W1 + l * DD * DD, b1 + l * DD, NND);
        cudaMemsetAsync(stats, 0, sizeof(float) * 2 * DD);
        k_stats<<<256, 256>>>(Z);
        k_bnrelu<<<gridElem, 256>>>(Y, Z, g1 + l * DD, be1 + l * DD);

        k_gemm<<<gridGemm, 256, smem_gemm>>>(Z, Y, W2 + l * DD * DD, b2 + l * DD, NND);
        cudaMemsetAsync(stats, 0, sizeof(float) * 2 * DD);
        k_stats<<<256, 256>>>(Z);
        k_bnrelu<<<gridElem, 256>>>(H, Z, g2 + l * DD, be2 + l * DD);

        k_gpool<<<gridNode, 256>>>(pg + (l + 1) * NG * DD, H, gids);
        hin = H;
    }

    k_readout<<<NG, OUTD>>>(out, predW, predb);
}